// round 14
// baseline (speedup 1.0000x reference)
#include <cuda_runtime.h>
#include <stdint.h>

#define N_   32
#define H_   56
#define W_   56
#define C_   256
#define HP   58          /* padded height */
#define WP   58          /* padded width (logical) */
#define WPS  64          /* padded row stride in words (aligned) */
#define COUT 256
#define NTAP 9
#define NWRD 72          /* 9 taps * 8 cin-groups */
#define NXP  (N_ * HP * WPS)        /* words per bit-plane = 118784 */
#define NPIXP (N_ * HP * WP)        /* padded pixels = 107648 */
#define NTILES (N_ * H_ * 7)        /* 8-pixel tiles = 12544 */

// Scratch (device globals — no allocation allowed)
__device__ uint32_t g_kbits[NWRD * COUT];
__device__ float    g_kpart[NWRD * COUT];
__device__ uint32_t g_xbt [8 * NXP];        // planar packed x sign bits
__device__ float    g_betap[NXP];           // sum |x| per padded pixel
__device__ unsigned g_ctr[4];               // per-cout-group tile counters

// ---------------------------------------------------------------------------
// Fused prep: blocks [0,72) binarize the kernel (+|k| partials);
// blocks [72, 72+13456) binarize padded x (+per-pixel sum|x|).
// Block 0 also resets the tile counters for this launch (graph-replay safe).
__global__ void prep_fused(const float* __restrict__ x,
                           const float* __restrict__ k) {
    if (blockIdx.x < NWRD) {
        if (blockIdx.x == 0 && threadIdx.x < 4) g_ctr[threadIdx.x] = 0u;
        // ---- kernel prep: block w covers cin rows [w*32, w*32+32) ----
        int w  = blockIdx.x;
        int co = threadIdx.x;
        const float* base = k + (size_t)w * 32 * COUT + co;
        uint32_t bits = 0;
        float s = 0.f;
#pragma unroll
        for (int b = 0; b < 32; b++) {
            float v = base[(size_t)b * COUT];
            if (v > 0.f) bits |= (1u << b);
            s += fabsf(v);
        }
        g_kbits[w * COUT + co] = bits;
        g_kpart[w * COUT + co] = s;
        return;
    }

    // ---- x prep: one warp per padded pixel ----
    int pix  = (blockIdx.x - NWRD) * 8 + (threadIdx.x >> 5);
    int lane = threadIdx.x & 31;
    if (pix >= NPIXP) return;
    int n  = pix / (HP * WP);
    int r  = pix % (HP * WP);
    int hp = r / WP, wp = r % WP;
    int ppos = (n * HP + hp) * WPS + wp;
    if (hp >= 1 && hp <= H_ && wp >= 1 && wp <= W_) {
        const float* xp = x + (((size_t)n * H_ + (hp - 1)) * W_ + (wp - 1)) * C_;
        float asum = 0.f;
        uint32_t bm[8];
#pragma unroll
        for (int j = 0; j < 8; j++) {
            float v = xp[j * 32 + lane];
            bm[j] = __ballot_sync(0xffffffffu, v > 0.f);
            asum += fabsf(v);
        }
#pragma unroll
        for (int o = 16; o; o >>= 1) asum += __shfl_xor_sync(0xffffffffu, asum, o);
#pragma unroll
        for (int j = 0; j < 8; j++)
            if (lane == j) g_xbt[(size_t)j * NXP + ppos] = bm[j];
        if (lane == 0) g_betap[ppos] = asum;
    } else {
        if (lane < 8) g_xbt[(size_t)lane * NXP + ppos] = 0u;
        if (lane == 0) g_betap[ppos] = 0.f;
    }
}

// ---------------------------------------------------------------------------
// Main XNOR-popcount conv with kw-level carry-save adder — exact R6 body
// (measured best: 349.8us). R14 delta: one-wave grid (148,4) + per-warp
// DYNAMIC tile stealing via g_ctr[cg] (atomic pipelined one tile ahead, so
// ATOMG latency hides behind the ~2900cyc tile compute). Eliminates the
// 0.25-wave static tail without R11's no-refill starvation.
__global__ void __launch_bounds__(256, 4) binconv_main(
        const float* __restrict__ bias, float* __restrict__ out) {
    extern __shared__ uint32_t s_k[];   // NWRD*64 words + 64 alpha floats
    float* s_alpha = (float*)(s_k + NWRD * 64);

    const int cg = blockIdx.y;
    {   // cooperative vectorized smem fill of this cg's kbits slice
        const uint4* src = (const uint4*)g_kbits;
        uint4*       dst = (uint4*)s_k;
        for (int m = threadIdx.x; m < NWRD * 16; m += 256) {
            int w = m >> 4, j = m & 15;
            dst[m] = src[w * 64 + cg * 16 + j];
        }
    }
    {   // inline alpha for this cg's 64 couts: 4 threads per cout, 18 terms each
        int col = threadIdx.x >> 2;          // 0..63
        int q   = threadIdx.x & 3;
        const float* kp = g_kpart + (size_t)(q * 18) * COUT + cg * 64 + col;
        float s = 0.f;
#pragma unroll
        for (int w = 0; w < 18; w++) s += kp[(size_t)w * COUT];
        s += __shfl_xor_sync(0xffffffffu, s, 1);
        s += __shfl_xor_sync(0xffffffffu, s, 2);
        if (q == 0) s_alpha[col] = s * (1.f / (NTAP * C_));
    }
    __syncthreads();

    const int lane = threadIdx.x & 31;
    const int co0  = cg * 64 + 2 * lane;

    const float2 al = *(const float2*)(s_alpha + 2 * lane);
    const float2 bi = *(const float2*)(bias + co0);

    // first tile grab
    unsigned t;
    if (lane == 0) t = atomicAdd(&g_ctr[cg], 1u);
    t = __shfl_sync(0xffffffffu, t, 0);

    while (t < NTILES) {
        // pipeline: issue grab for the NEXT tile now; consume after compute
        unsigned nt;
        if (lane == 0) nt = atomicAdd(&g_ctr[cg], 1u);

        int tw = t % 7;
        int tr = t / 7;
        int th = tr % H_;
        int n  = tr / H_;
        int rb = (n * HP + th) * WPS + tw * 8;

        // packed 16-bit accumulators: lo16 = co0, hi16 = co0+1
        uint32_t accS[8] = {0,0,0,0,0,0,0,0};    // weight-1 popcounts (<= 768)
        uint32_t accM[8] = {0,0,0,0,0,0,0,0};    // weight-2 popcounts (<= 768)

#pragma unroll 2
        for (int gc = 0; gc < 8; gc++) {
            const uint32_t* xplane = g_xbt + (size_t)gc * NXP + rb;
#pragma unroll
            for (int kh = 0; kh < 3; kh++) {
                const uint4* xr = (const uint4*)(xplane + kh * WPS);
                uint4 q0 = xr[0], q1 = xr[1], q2 = xr[2];
                uint32_t xw[12] = {q0.x, q0.y, q0.z, q0.w,
                                   q1.x, q1.y, q1.z, q1.w,
                                   q2.x, q2.y, q2.z, q2.w};
                const uint2* k0 = (const uint2*)(s_k + ((kh * 3 + 0) * 8 + gc) * 64);
                const uint2* k1 = (const uint2*)(s_k + ((kh * 3 + 1) * 8 + gc) * 64);
                const uint2* k2 = (const uint2*)(s_k + ((kh * 3 + 2) * 8 + gc) * 64);
                uint2 kv0 = k0[lane], kv1 = k1[lane], kv2 = k2[lane];
#pragma unroll
                for (int p = 0; p < 8; p++) {
                    uint32_t t0 = xw[p] ^ kv0.x;
                    uint32_t t1 = xw[p + 1] ^ kv1.x;
                    uint32_t t2 = xw[p + 2] ^ kv2.x;
                    uint32_t s0 = t0 ^ t1 ^ t2;                      // LOP3 0x96
                    uint32_t m0 = (t0 & t1) | (t0 & t2) | (t1 & t2); // LOP3 0xE8
                    uint32_t u0 = xw[p] ^ kv0.y;
                    uint32_t u1 = xw[p + 1] ^ kv1.y;
                    uint32_t u2 = xw[p + 2] ^ kv2.y;
                    uint32_t s1 = u0 ^ u1 ^ u2;
                    uint32_t m1 = (u0 & u1) | (u0 & u2) | (u1 & u2);
                    accS[p] += (uint32_t)__popc(s0) + ((uint32_t)__popc(s1) << 16);
                    accM[p] += (uint32_t)__popc(m0) + ((uint32_t)__popc(m1) << 16);
                }
            }
        }

        // Epilogue: ksum[p] = 3x3 window sum of beta; out = dot*K*alpha + bias
        const float* bp = g_betap + rb;
        float rs[10];
        {
            float4 a = *(const float4*)(bp);
            float4 b = *(const float4*)(bp + WPS);
            float4 c = *(const float4*)(bp + 2 * WPS);
            rs[0] = a.x + b.x + c.x;  rs[1] = a.y + b.y + c.y;
            rs[2] = a.z + b.z + c.z;  rs[3] = a.w + b.w + c.w;
        }
        {
            float4 a = *(const float4*)(bp + 4);
            float4 b = *(const float4*)(bp + WPS + 4);
            float4 c = *(const float4*)(bp + 2 * WPS + 4);
            rs[4] = a.x + b.x + c.x;  rs[5] = a.y + b.y + c.y;
            rs[6] = a.z + b.z + c.z;  rs[7] = a.w + b.w + c.w;
        }
        {
            float2 a = *(const float2*)(bp + 8);
            float2 b = *(const float2*)(bp + WPS + 8);
            float2 c = *(const float2*)(bp + 2 * WPS + 8);
            rs[8] = a.x + b.x + c.x;  rs[9] = a.y + b.y + c.y;
        }

        float* op = out + (size_t)t * 8 * COUT + co0;
#pragma unroll
        for (int p = 0; p < 8; p++) {
            float ks = (rs[p] + rs[p + 1] + rs[p + 2]) * (1.f / 2304.f);
            uint32_t T0 = (accS[p] & 0xFFFFu) + 2u * (accM[p] & 0xFFFFu);
            uint32_t T1 = (accS[p] >> 16)     + 2u * (accM[p] >> 16);
            float d0 = 2304.f - 2.f * (float)T0;
            float d1 = 2304.f - 2.f * (float)T1;
            float2 o;
            o.x = d0 * (ks * al.x) + bi.x;
            o.y = d1 * (ks * al.y) + bi.y;
            *(float2*)(op + (size_t)p * COUT) = o;
        }

        // consume the pipelined grab
        t = __shfl_sync(0xffffffffu, nt, 0);
    }
}

// ---------------------------------------------------------------------------
extern "C" void kernel_launch(void* const* d_in, const int* in_sizes, int n_in,
                              void* d_out, int out_size) {
    (void)in_sizes; (void)n_in; (void)out_size;
    const float* x    = (const float*)d_in[0];
    const float* kern = (const float*)d_in[1];
    const float* bias = (const float*)d_in[2];
    float*       out  = (float*)d_out;

    // one fused prep launch: 72 k-prep blocks + 13456 x-prep blocks
    prep_fused<<<NWRD + NPIXP / 8, 256>>>(x, kern);

    const size_t smem_bytes = (size_t)NWRD * 64 * 4 + 64 * 4;   // 18688
    dim3 grid(148, 4);   // 592 blocks = one full wave; dynamic stealing inside
    binconv_main<<<grid, 256, smem_bytes>>>(bias, out);
}

// round 15
// speedup vs baseline: 1.6748x; 1.6748x over previous
#include <cuda_runtime.h>
#include <stdint.h>

#define N_   32
#define H_   56
#define W_   56
#define C_   256
#define HP   58          /* padded height */
#define WP   58          /* padded width (logical) */
#define WPS  64          /* padded row stride in words (aligned) */
#define COUT 256
#define NTAP 9
#define NWRD 72          /* 9 taps * 8 cin-groups */
#define NXP  (N_ * HP * WPS)        /* words per bit-plane = 118784 */
#define NPIXP (N_ * HP * WP)        /* padded pixels = 107648 */
#define NTILES (N_ * H_ * 7)        /* 8-pixel tiles = 12544 */
#define NGRP  (NTILES / 8)          /* warp-groups of 8 tiles = 1568 */

// Scratch (device globals — no allocation allowed)
__device__ uint32_t g_kbits[NWRD * COUT];
__device__ float    g_kpart[NWRD * COUT];
__device__ uint32_t g_xbt [8 * NXP];        // planar packed x sign bits
__device__ float    g_betap[NXP];           // sum |x| per padded pixel

// pack two popcounts into lo/hi 16 via IMAD on the fma pipe (alu is binder)
__device__ __forceinline__ uint32_t pack16(uint32_t lo, uint32_t hi) {
    uint32_t r;
    asm("mad.lo.s32 %0, %1, 0x10000, %2;" : "=r"(r) : "r"(hi), "r"(lo));
    return r;
}

// ---------------------------------------------------------------------------
// Fused prep: blocks [0,72) binarize the kernel (+|k| partials);
// blocks [72, 72+13456) binarize padded x (+per-pixel sum|x|), with the
// bit-plane stores staged through smem so they go out coalesced.
__global__ void prep_fused(const float* __restrict__ x,
                           const float* __restrict__ k) {
    if (blockIdx.x < NWRD) {
        // ---- kernel prep: block w covers cin rows [w*32, w*32+32) ----
        int w  = blockIdx.x;
        int co = threadIdx.x;
        const float* base = k + (size_t)w * 32 * COUT + co;
        uint32_t bits = 0;
        float s = 0.f;
#pragma unroll
        for (int b = 0; b < 32; b++) {
            float v = base[(size_t)b * COUT];
            if (v > 0.f) bits |= (1u << b);
            s += fabsf(v);
        }
        g_kbits[w * COUT + co] = bits;
        g_kpart[w * COUT + co] = s;
        return;
    }

    // ---- x prep: one warp per padded pixel, 8 pixels per block ----
    __shared__ uint32_t sb[8][8];     // [pixel-in-block][plane]
    __shared__ float    sbeta[8];
    __shared__ int      sppos[8];

    int warp = threadIdx.x >> 5;
    int lane = threadIdx.x & 31;
    int pix  = (blockIdx.x - NWRD) * 8 + warp;    // NPIXP divisible by 8

    {
        int n  = pix / (HP * WP);
        int r  = pix % (HP * WP);
        int hp = r / WP, wp = r % WP;
        int ppos = (n * HP + hp) * WPS + wp;
        if (lane == 0) sppos[warp] = ppos;

        if (hp >= 1 && hp <= H_ && wp >= 1 && wp <= W_) {
            const float* xp = x + (((size_t)n * H_ + (hp - 1)) * W_ + (wp - 1)) * C_;
            float asum = 0.f;
            uint32_t bm[8];
#pragma unroll
            for (int j = 0; j < 8; j++) {
                float v = xp[j * 32 + lane];
                bm[j] = __ballot_sync(0xffffffffu, v > 0.f);
                asum += fabsf(v);
            }
#pragma unroll
            for (int o = 16; o; o >>= 1) asum += __shfl_xor_sync(0xffffffffu, asum, o);
            if (lane < 8) sb[warp][lane] = bm[lane];
            if (lane == 0) sbeta[warp] = asum;
        } else {
            if (lane < 8) sb[warp][lane] = 0u;
            if (lane == 0) sbeta[warp] = 0.f;
        }
    }
    __syncthreads();

    // coalesced write-out: thread tid<64 -> plane j = tid>>3, pixel q = tid&7
    if (threadIdx.x < 64) {
        int j = threadIdx.x >> 3, q = threadIdx.x & 7;
        g_xbt[(size_t)j * NXP + sppos[q]] = sb[q][j];
    }
    if (threadIdx.x < 8)
        g_betap[sppos[threadIdx.x]] = sbeta[threadIdx.x];
}

// ---------------------------------------------------------------------------
// Main XNOR-popcount conv with kw-level carry-save adder — exact R13 body
// (measured best: 350.8us main). R15 delta: the lo/hi16 pack goes through
// mad.lo.s32 (IMAD -> fma pipe) instead of LEA+IADD3 on the saturated alu.
__global__ void __launch_bounds__(256, 4) binconv_main(
        const float* __restrict__ bias, float* __restrict__ out) {
    extern __shared__ uint32_t s_k[];   // NWRD*64 words + 64 alpha floats
    float* s_alpha = (float*)(s_k + NWRD * 64);

    const int cg = blockIdx.y;
    {   // cooperative vectorized smem fill of this cg's kbits slice
        const uint4* src = (const uint4*)g_kbits;
        uint4*       dst = (uint4*)s_k;
        for (int m = threadIdx.x; m < NWRD * 16; m += 256) {
            int w = m >> 4, j = m & 15;
            dst[m] = src[w * 64 + cg * 16 + j];
        }
    }
    {   // inline alpha for this cg's 64 couts: 4 threads per cout, 18 terms each
        int col = threadIdx.x >> 2;          // 0..63
        int q   = threadIdx.x & 3;
        const float* kp = g_kpart + (size_t)(q * 18) * COUT + cg * 64 + col;
        float s = 0.f;
#pragma unroll
        for (int w = 0; w < 18; w++) s += kp[(size_t)w * COUT];
        s += __shfl_xor_sync(0xffffffffu, s, 1);
        s += __shfl_xor_sync(0xffffffffu, s, 2);
        if (q == 0) s_alpha[col] = s * (1.f / (NTAP * C_));
    }
    __syncthreads();

    const int warp = threadIdx.x >> 5;
    const int lane = threadIdx.x & 31;
    const int co0  = cg * 64 + 2 * lane;

    const float2 al = *(const float2*)(s_alpha + 2 * lane);
    const float2 bi = *(const float2*)(bias + co0);

    for (int grp = blockIdx.x; grp < NGRP; grp += gridDim.x) {
        int t  = grp * 8 + warp;
        int tw = t % 7;
        int tr = t / 7;
        int th = tr % H_;
        int n  = tr / H_;
        int rb = (n * HP + th) * WPS + tw * 8;

        // packed 16-bit accumulators: lo16 = co0, hi16 = co0+1
        uint32_t accS[8] = {0,0,0,0,0,0,0,0};    // weight-1 popcounts (<= 768)
        uint32_t accM[8] = {0,0,0,0,0,0,0,0};    // weight-2 popcounts (<= 768)

#pragma unroll 2
        for (int gc = 0; gc < 8; gc++) {
            const uint32_t* xplane = g_xbt + (size_t)gc * NXP + rb;
#pragma unroll
            for (int kh = 0; kh < 3; kh++) {
                const uint4* xr = (const uint4*)(xplane + kh * WPS);
                uint4 q0 = xr[0], q1 = xr[1], q2 = xr[2];
                uint32_t xw[12] = {q0.x, q0.y, q0.z, q0.w,
                                   q1.x, q1.y, q1.z, q1.w,
                                   q2.x, q2.y, q2.z, q2.w};
                const uint2* k0 = (const uint2*)(s_k + ((kh * 3 + 0) * 8 + gc) * 64);
                const uint2* k1 = (const uint2*)(s_k + ((kh * 3 + 1) * 8 + gc) * 64);
                const uint2* k2 = (const uint2*)(s_k + ((kh * 3 + 2) * 8 + gc) * 64);
                uint2 kv0 = k0[lane], kv1 = k1[lane], kv2 = k2[lane];
#pragma unroll
                for (int p = 0; p < 8; p++) {
                    uint32_t t0 = xw[p] ^ kv0.x;
                    uint32_t t1 = xw[p + 1] ^ kv1.x;
                    uint32_t t2 = xw[p + 2] ^ kv2.x;
                    uint32_t s0 = t0 ^ t1 ^ t2;                      // LOP3 0x96
                    uint32_t m0 = (t0 & t1) | (t0 & t2) | (t1 & t2); // LOP3 0xE8
                    uint32_t u0 = xw[p] ^ kv0.y;
                    uint32_t u1 = xw[p + 1] ^ kv1.y;
                    uint32_t u2 = xw[p + 2] ^ kv2.y;
                    uint32_t s1 = u0 ^ u1 ^ u2;
                    uint32_t m1 = (u0 & u1) | (u0 & u2) | (u1 & u2);
                    accS[p] += pack16((uint32_t)__popc(s0), (uint32_t)__popc(s1));
                    accM[p] += pack16((uint32_t)__popc(m0), (uint32_t)__popc(m1));
                }
            }
        }

        // Epilogue: ksum[p] = 3x3 window sum of beta; out = dot*K*alpha + bias
        const float* bp = g_betap + rb;
        float rs[10];
        {
            float4 a = *(const float4*)(bp);
            float4 b = *(const float4*)(bp + WPS);
            float4 c = *(const float4*)(bp + 2 * WPS);
            rs[0] = a.x + b.x + c.x;  rs[1] = a.y + b.y + c.y;
            rs[2] = a.z + b.z + c.z;  rs[3] = a.w + b.w + c.w;
        }
        {
            float4 a = *(const float4*)(bp + 4);
            float4 b = *(const float4*)(bp + WPS + 4);
            float4 c = *(const float4*)(bp + 2 * WPS + 4);
            rs[4] = a.x + b.x + c.x;  rs[5] = a.y + b.y + c.y;
            rs[6] = a.z + b.z + c.z;  rs[7] = a.w + b.w + c.w;
        }
        {
            float2 a = *(const float2*)(bp + 8);
            float2 b = *(const float2*)(bp + WPS + 8);
            float2 c = *(const float2*)(bp + 2 * WPS + 8);
            rs[8] = a.x + b.x + c.x;  rs[9] = a.y + b.y + c.y;
        }

        float* op = out + (size_t)t * 8 * COUT + co0;
#pragma unroll
        for (int p = 0; p < 8; p++) {
            float ks = (rs[p] + rs[p + 1] + rs[p + 2]) * (1.f / 2304.f);
            uint32_t T0 = (accS[p] & 0xFFFFu) + 2u * (accM[p] & 0xFFFFu);
            uint32_t T1 = (accS[p] >> 16)     + 2u * (accM[p] >> 16);
            float d0 = 2304.f - 2.f * (float)T0;
            float d1 = 2304.f - 2.f * (float)T1;
            float2 o;
            o.x = d0 * (ks * al.x) + bi.x;
            o.y = d1 * (ks * al.y) + bi.y;
            *(float2*)(op + (size_t)p * COUT) = o;
        }
    }
}

// ---------------------------------------------------------------------------
extern "C" void kernel_launch(void* const* d_in, const int* in_sizes, int n_in,
                              void* d_out, int out_size) {
    (void)in_sizes; (void)n_in; (void)out_size;
    const float* x    = (const float*)d_in[0];
    const float* kern = (const float*)d_in[1];
    const float* bias = (const float*)d_in[2];
    float*       out  = (float*)d_out;

    // one fused prep launch: 72 k-prep blocks + 13456 x-prep blocks
    prep_fused<<<NWRD + NPIXP / 8, 256>>>(x, kern);

    const size_t smem_bytes = (size_t)NWRD * 64 * 4 + 64 * 4;   // 18688
    dim3 grid(185, 4);   // 740 blocks @ 4 CTAs/SM (measured-best config, R13)
    binconv_main<<<grid, 256, smem_bytes>>>(bias, out);
}

// round 16
// speedup vs baseline: 1.7008x; 1.0155x over previous
#include <cuda_runtime.h>
#include <stdint.h>

#define N_   32
#define H_   56
#define W_   56
#define C_   256
#define HP   58          /* padded height */
#define WP   58          /* padded width (logical) */
#define WPS  64          /* padded row stride in words (aligned) */
#define COUT 256
#define NTAP 9
#define NWRD 72          /* 9 taps * 8 cin-groups */
#define NXP  (N_ * HP * WPS)        /* words per bit-plane = 118784 */
#define NPIXP (N_ * HP * WP)        /* padded pixels = 107648 */
#define NTILES (N_ * H_ * 7)        /* 8-pixel tiles = 12544 */
#define NGRP  (NTILES / 8)          /* warp-groups of 8 tiles = 1568 */

// Scratch (device globals — no allocation allowed)
__device__ uint32_t g_kbits[NWRD * COUT];
__device__ float    g_kpart[NWRD * COUT];
__device__ uint32_t g_xbt [8 * NXP];        // planar packed x sign bits
__device__ float    g_betap[NXP];           // sum |x| per padded pixel

// ---------------------------------------------------------------------------
// Fused prep (R15 measured-best): blocks [0,72) binarize the kernel
// (+|k| partials); blocks [72,...) binarize padded x with bit-plane stores
// staged through smem so they go out coalesced.
__global__ void prep_fused(const float* __restrict__ x,
                           const float* __restrict__ k) {
    if (blockIdx.x < NWRD) {
        // ---- kernel prep: block w covers cin rows [w*32, w*32+32) ----
        int w  = blockIdx.x;
        int co = threadIdx.x;
        const float* base = k + (size_t)w * 32 * COUT + co;
        uint32_t bits = 0;
        float s = 0.f;
#pragma unroll
        for (int b = 0; b < 32; b++) {
            float v = base[(size_t)b * COUT];
            if (v > 0.f) bits |= (1u << b);
            s += fabsf(v);
        }
        g_kbits[w * COUT + co] = bits;
        g_kpart[w * COUT + co] = s;
        return;
    }

    // ---- x prep: one warp per padded pixel, 8 pixels per block ----
    __shared__ uint32_t sb[8][8];     // [pixel-in-block][plane]
    __shared__ float    sbeta[8];
    __shared__ int      sppos[8];

    int warp = threadIdx.x >> 5;
    int lane = threadIdx.x & 31;
    int pix  = (blockIdx.x - NWRD) * 8 + warp;    // NPIXP divisible by 8

    {
        int n  = pix / (HP * WP);
        int r  = pix % (HP * WP);
        int hp = r / WP, wp = r % WP;
        int ppos = (n * HP + hp) * WPS + wp;
        if (lane == 0) sppos[warp] = ppos;

        if (hp >= 1 && hp <= H_ && wp >= 1 && wp <= W_) {
            const float* xp = x + (((size_t)n * H_ + (hp - 1)) * W_ + (wp - 1)) * C_;
            float asum = 0.f;
            uint32_t bm[8];
#pragma unroll
            for (int j = 0; j < 8; j++) {
                float v = xp[j * 32 + lane];
                bm[j] = __ballot_sync(0xffffffffu, v > 0.f);
                asum += fabsf(v);
            }
#pragma unroll
            for (int o = 16; o; o >>= 1) asum += __shfl_xor_sync(0xffffffffu, asum, o);
            if (lane < 8) sb[warp][lane] = bm[lane];
            if (lane == 0) sbeta[warp] = asum;
        } else {
            if (lane < 8) sb[warp][lane] = 0u;
            if (lane == 0) sbeta[warp] = 0.f;
        }
    }
    __syncthreads();

    // coalesced write-out: thread tid<64 -> plane j = tid>>3, pixel q = tid&7
    if (threadIdx.x < 64) {
        int j = threadIdx.x >> 3, q = threadIdx.x & 7;
        g_xbt[(size_t)j * NXP + sppos[q]] = sb[q][j];
    }
    if (threadIdx.x < 8)
        g_betap[sppos[threadIdx.x]] = sbeta[threadIdx.x];
}

// ---------------------------------------------------------------------------
// Main XNOR-popcount conv with kw-level carry-save adder — EXACT R13 body
// (measured best main: 350.8us; R15's mad.lo pack regressed it, reverted).
__global__ void __launch_bounds__(256, 4) binconv_main(
        const float* __restrict__ bias, float* __restrict__ out) {
    extern __shared__ uint32_t s_k[];   // NWRD*64 words + 64 alpha floats
    float* s_alpha = (float*)(s_k + NWRD * 64);

    const int cg = blockIdx.y;
    {   // cooperative vectorized smem fill of this cg's kbits slice
        const uint4* src = (const uint4*)g_kbits;
        uint4*       dst = (uint4*)s_k;
        for (int m = threadIdx.x; m < NWRD * 16; m += 256) {
            int w = m >> 4, j = m & 15;
            dst[m] = src[w * 64 + cg * 16 + j];
        }
    }
    {   // inline alpha for this cg's 64 couts: 4 threads per cout, 18 terms each
        int col = threadIdx.x >> 2;          // 0..63
        int q   = threadIdx.x & 3;
        const float* kp = g_kpart + (size_t)(q * 18) * COUT + cg * 64 + col;
        float s = 0.f;
#pragma unroll
        for (int w = 0; w < 18; w++) s += kp[(size_t)w * COUT];
        s += __shfl_xor_sync(0xffffffffu, s, 1);
        s += __shfl_xor_sync(0xffffffffu, s, 2);
        if (q == 0) s_alpha[col] = s * (1.f / (NTAP * C_));
    }
    __syncthreads();

    const int warp = threadIdx.x >> 5;
    const int lane = threadIdx.x & 31;
    const int co0  = cg * 64 + 2 * lane;

    const float2 al = *(const float2*)(s_alpha + 2 * lane);
    const float2 bi = *(const float2*)(bias + co0);

    for (int grp = blockIdx.x; grp < NGRP; grp += gridDim.x) {
        int t  = grp * 8 + warp;
        int tw = t % 7;
        int tr = t / 7;
        int th = tr % H_;
        int n  = tr / H_;
        int rb = (n * HP + th) * WPS + tw * 8;

        // packed 16-bit accumulators: lo16 = co0, hi16 = co0+1
        uint32_t accS[8] = {0,0,0,0,0,0,0,0};    // weight-1 popcounts (<= 768)
        uint32_t accM[8] = {0,0,0,0,0,0,0,0};    // weight-2 popcounts (<= 768)

#pragma unroll 2
        for (int gc = 0; gc < 8; gc++) {
            const uint32_t* xplane = g_xbt + (size_t)gc * NXP + rb;
#pragma unroll
            for (int kh = 0; kh < 3; kh++) {
                const uint4* xr = (const uint4*)(xplane + kh * WPS);
                uint4 q0 = xr[0], q1 = xr[1], q2 = xr[2];
                uint32_t xw[12] = {q0.x, q0.y, q0.z, q0.w,
                                   q1.x, q1.y, q1.z, q1.w,
                                   q2.x, q2.y, q2.z, q2.w};
                const uint2* k0 = (const uint2*)(s_k + ((kh * 3 + 0) * 8 + gc) * 64);
                const uint2* k1 = (const uint2*)(s_k + ((kh * 3 + 1) * 8 + gc) * 64);
                const uint2* k2 = (const uint2*)(s_k + ((kh * 3 + 2) * 8 + gc) * 64);
                uint2 kv0 = k0[lane], kv1 = k1[lane], kv2 = k2[lane];
#pragma unroll
                for (int p = 0; p < 8; p++) {
                    uint32_t t0 = xw[p] ^ kv0.x;
                    uint32_t t1 = xw[p + 1] ^ kv1.x;
                    uint32_t t2 = xw[p + 2] ^ kv2.x;
                    uint32_t s0 = t0 ^ t1 ^ t2;                      // LOP3 0x96
                    uint32_t m0 = (t0 & t1) | (t0 & t2) | (t1 & t2); // LOP3 0xE8
                    uint32_t u0 = xw[p] ^ kv0.y;
                    uint32_t u1 = xw[p + 1] ^ kv1.y;
                    uint32_t u2 = xw[p + 2] ^ kv2.y;
                    uint32_t s1 = u0 ^ u1 ^ u2;
                    uint32_t m1 = (u0 & u1) | (u0 & u2) | (u1 & u2);
                    accS[p] += (uint32_t)__popc(s0) + ((uint32_t)__popc(s1) << 16);
                    accM[p] += (uint32_t)__popc(m0) + ((uint32_t)__popc(m1) << 16);
                }
            }
        }

        // Epilogue: ksum[p] = 3x3 window sum of beta; out = dot*K*alpha + bias
        const float* bp = g_betap + rb;
        float rs[10];
        {
            float4 a = *(const float4*)(bp);
            float4 b = *(const float4*)(bp + WPS);
            float4 c = *(const float4*)(bp + 2 * WPS);
            rs[0] = a.x + b.x + c.x;  rs[1] = a.y + b.y + c.y;
            rs[2] = a.z + b.z + c.z;  rs[3] = a.w + b.w + c.w;
        }
        {
            float4 a = *(const float4*)(bp + 4);
            float4 b = *(const float4*)(bp + WPS + 4);
            float4 c = *(const float4*)(bp + 2 * WPS + 4);
            rs[4] = a.x + b.x + c.x;  rs[5] = a.y + b.y + c.y;
            rs[6] = a.z + b.z + c.z;  rs[7] = a.w + b.w + c.w;
        }
        {
            float2 a = *(const float2*)(bp + 8);
            float2 b = *(const float2*)(bp + WPS + 8);
            float2 c = *(const float2*)(bp + 2 * WPS + 8);
            rs[8] = a.x + b.x + c.x;  rs[9] = a.y + b.y + c.y;
        }

        float* op = out + (size_t)t * 8 * COUT + co0;
#pragma unroll
        for (int p = 0; p < 8; p++) {
            float ks = (rs[p] + rs[p + 1] + rs[p + 2]) * (1.f / 2304.f);
            uint32_t T0 = (accS[p] & 0xFFFFu) + 2u * (accM[p] & 0xFFFFu);
            uint32_t T1 = (accS[p] >> 16)     + 2u * (accM[p] >> 16);
            float d0 = 2304.f - 2.f * (float)T0;
            float d1 = 2304.f - 2.f * (float)T1;
            float2 o;
            o.x = d0 * (ks * al.x) + bi.x;
            o.y = d1 * (ks * al.y) + bi.y;
            *(float2*)(op + (size_t)p * COUT) = o;
        }
    }
}

// ---------------------------------------------------------------------------
extern "C" void kernel_launch(void* const* d_in, const int* in_sizes, int n_in,
                              void* d_out, int out_size) {
    (void)in_sizes; (void)n_in; (void)out_size;
    const float* x    = (const float*)d_in[0];
    const float* kern = (const float*)d_in[1];
    const float* bias = (const float*)d_in[2];
    float*       out  = (float*)d_out;

    // one fused prep launch: 72 k-prep blocks + 13456 x-prep blocks
    prep_fused<<<NWRD + NPIXP / 8, 256>>>(x, kern);

    const size_t smem_bytes = (size_t)NWRD * 64 * 4 + 64 * 4;   // 18688
    dim3 grid(185, 4);   // 740 blocks @ 4 CTAs/SM (measured-best config, R13)
    binconv_main<<<grid, 256, smem_bytes>>>(bias, out);
}